// round 3
// baseline (speedup 1.0000x reference)
#include <cuda_runtime.h>

#define HH 512
#define WW 512
#define NB 8
#define NMODES 8
#define CW 16     // WIDTH
#define HID 64
#define TWO_PI_OVER_N 0.012271846303085129f  // 2*pi/512

// ---------------- scratch (static device globals; no allocation) -------------
__device__ float  g_R[NB * HH * 16];                 // row DFT of x: [b][h][2*ky{re,im}]
__device__ float  g_Xx[NB * NMODES * NMODES * 2];    // DFT(x): [b][kx][ky]{re,im} (1/N^2 folded)
__device__ float2 g_Z[NB * HID * NMODES * NMODES];   // folded modes: [b][j][kx][ky]
__device__ float  g_alpha[HID];
__device__ float  g_beta[HID];

__device__ __forceinline__ float warp_sum(float v) {
#pragma unroll
    for (int o = 16; o > 0; o >>= 1) v += __shfl_xor_sync(0xffffffffu, v, o);
    return v;
}

// ---------------- stage 1a: per-row partial DFT of x (over w, 8 modes) -------
__global__ void __launch_bounds__(256) k_rowdft(const float* __restrict__ x) {
    const int b = blockIdx.y, h = blockIdx.x;
    const int tid = threadIdx.x;
    const float* row = x + ((size_t)b * HH + h) * WW;

    float vr[8], vi[8];
#pragma unroll
    for (int k = 0; k < 8; k++) { vr[k] = 0.f; vi[k] = 0.f; }

    for (int w = tid; w < WW; w += 256) {
        float xv = row[w];
        float s1, c1;
        __sincosf((float)w * TWO_PI_OVER_N, &s1, &c1);
        float ck = 1.f, sk = 0.f;  // e^{-i k th}: accumulate (x*cos, -x*sin)
#pragma unroll
        for (int k = 0; k < 8; k++) {
            vr[k] += xv * ck;
            vi[k] -= xv * sk;
            float cn = ck * c1 - sk * s1;
            float sn = sk * c1 + ck * s1;
            ck = cn; sk = sn;
        }
    }

    float vals[16];
#pragma unroll
    for (int k = 0; k < 8; k++) { vals[2 * k] = vr[k]; vals[2 * k + 1] = vi[k]; }
#pragma unroll
    for (int i = 0; i < 16; i++) vals[i] = warp_sum(vals[i]);

    __shared__ float red[8][16];
    int lane = tid & 31, warp = tid >> 5;
    if (lane == 0) {
#pragma unroll
        for (int i = 0; i < 16; i++) red[warp][i] = vals[i];
    }
    __syncthreads();
    if (tid < 16) {
        float s = 0.f;
#pragma unroll
        for (int w = 0; w < 8; w++) s += red[w][tid];
        g_R[((size_t)b * HH + h) * 16 + tid] = s;
    }
}

// ---------------- stage 1b: column DFT (over h) -> Xx[b][kx][ky] -------------
__global__ void __launch_bounds__(256) k_coldft() {
    const int b = blockIdx.x >> 3, ky = blockIdx.x & 7;
    const int tid = threadIdx.x;

    float vr[8], vi[8];
#pragma unroll
    for (int k = 0; k < 8; k++) { vr[k] = 0.f; vi[k] = 0.f; }

    for (int h = tid; h < HH; h += 256) {
        float rr = g_R[((size_t)b * HH + h) * 16 + 2 * ky];
        float ri = g_R[((size_t)b * HH + h) * 16 + 2 * ky + 1];
        float s1, c1;
        __sincosf((float)h * TWO_PI_OVER_N, &s1, &c1);
        float ck = 1.f, sk = 0.f;  // multiply by e^{-i kx th}
#pragma unroll
        for (int k = 0; k < 8; k++) {
            vr[k] += rr * ck + ri * sk;
            vi[k] += ri * ck - rr * sk;
            float cn = ck * c1 - sk * s1;
            float sn = sk * c1 + ck * s1;
            ck = cn; sk = sn;
        }
    }

    float vals[16];
#pragma unroll
    for (int k = 0; k < 8; k++) { vals[2 * k] = vr[k]; vals[2 * k + 1] = vi[k]; }
#pragma unroll
    for (int i = 0; i < 16; i++) vals[i] = warp_sum(vals[i]);

    __shared__ float red[8][16];
    int lane = tid & 31, warp = tid >> 5;
    if (lane == 0) {
#pragma unroll
        for (int i = 0; i < 16; i++) red[warp][i] = vals[i];
    }
    __syncthreads();
    if (tid < 16) {
        float s = 0.f;
#pragma unroll
        for (int w = 0; w < 8; w++) s += red[w][tid];
        int kx = tid >> 1;
        // layout: [b][kx][ky]{re,im}; fold forward norm 1/(H*W)
        g_Xx[(((size_t)b * 8 + kx) * 8 + ky) * 2 + (tid & 1)] = s * (1.f / (512.f * 512.f));
    }
}

// ---------------- stage 2a: affine chain (alpha/beta, batch independent) -----
__global__ void k_affine(const float* __restrict__ fc0_w, const float* __restrict__ fc0_b,
                         const float* __restrict__ conv_w, const float* __restrict__ conv_b,
                         const float* __restrict__ fc1_w, const float* __restrict__ fc1_b) {
    __shared__ float v[16], bb[16], nv[16], nb[16];
    int t = threadIdx.x;
    if (t < 16) { v[t] = fc0_w[t]; bb[t] = fc0_b[t]; }
    __syncthreads();
    for (int d = 0; d < 3; d++) {
        if (t < 16) {
            float sv = 0.f, sb = 0.f;
            for (int c = 0; c < 16; c++) {
                float cw = conv_w[d * 256 + t * 16 + c];
                sv += cw * v[c];
                sb += cw * bb[c];
            }
            nv[t] = sv;
            nb[t] = sb + conv_b[d * 16 + t];
        }
        __syncthreads();
        if (t < 16) { v[t] = nv[t]; bb[t] = nb[t]; }
        __syncthreads();
    }
    if (t < 64) {
        float a = 0.f, be = 0.f;
        for (int o = 0; o < 16; o++) {
            float f = fc1_w[o * 64 + t];
            a  += f * v[o];
            be += f * bb[o];
        }
        g_alpha[t] = a;
        g_beta[t]  = be + fc1_b[t];
    }
}

// ---------------- stage 2b: closed-form mode propagation per (b,kx,ky) site --
__global__ void k_modes(const float* __restrict__ spec_wr, const float* __restrict__ spec_wi,
                        const float* __restrict__ conv_w, const float* __restrict__ conv_b,
                        const float* __restrict__ fc0_w, const float* __restrict__ fc0_b,
                        const float* __restrict__ fc1_w) {
    const int site = blockIdx.x;     // b*64 + kx*8 + ky
    const int b = site >> 6;
    const int s = site & 63;
    const int kx = s >> 3, ky = s & 7;
    const bool dc = (s == 0);
    const int t = threadIdx.x;       // 64 threads

    __shared__ float2 X[16], Xn[16], Y[3][16], T[16];

    if (t < 16) {
        float xr = g_Xx[((size_t)(b * 8 + kx) * 8 + ky) * 2 + 0];
        float xi = g_Xx[((size_t)(b * 8 + kx) * 8 + ky) * 2 + 1];
        float w0 = fc0_w[t];
        X[t] = make_float2(w0 * xr + (dc ? fc0_b[t] : 0.f), w0 * xi);
    }
    __syncthreads();

    for (int d = 0; d < 3; d++) {
        if (t < 16) {
            const int o = t;
            float yr = 0.f, yi = 0.f;
            for (int c = 0; c < 16; c++) {
                int wi_ = ((d * 16 + c) * 16 + o) * 64 + kx * 8 + ky;
                float wr = spec_wr[wi_], wim = spec_wi[wi_];
                float xr = X[c].x, xi = X[c].y;
                yr += xr * wr - xi * wim;
                yi += xr * wim + xi * wr;
            }
            Y[d][o] = make_float2(yr, yi);
        }
        __syncthreads();
        if (t < 16) {
            const int o = t;
            float2 gy = Y[d][o];
            // DFT of the inverse transform of the kept band:
            if (ky == 0) {
                if (kx == 0) gy.y = 0.f;            // DC: Re(Y)
                else { gy.x *= 0.5f; gy.y *= 0.5f; } // ky=0, kx>0: Y/2
            }
            float nr = gy.x, ni = gy.y;
            for (int c = 0; c < 16; c++) {
                float cw = conv_w[d * 256 + o * 16 + c];
                nr += cw * X[c].x;
                ni += cw * X[c].y;
            }
            if (dc) nr += conv_b[d * 16 + o];
            Xn[o] = make_float2(nr, ni);
        }
        __syncthreads();
        if (t < 16) X[t] = Xn[t];
        __syncthreads();
    }

    // Ycomb = Y3 + C3*(Y2 + C2*Y1)
    if (t < 16) {
        const int o = t;
        float tr = Y[1][o].x, ti = Y[1][o].y;
        for (int c = 0; c < 16; c++) {
            float cw = conv_w[1 * 256 + o * 16 + c];
            tr += cw * Y[0][c].x;
            ti += cw * Y[0][c].y;
        }
        T[o] = make_float2(tr, ti);
    }
    __syncthreads();
    if (t < 16) {
        const int o = t;
        float yr = Y[2][o].x, yi = Y[2][o].y;
        for (int c = 0; c < 16; c++) {
            float cw = conv_w[2 * 256 + o * 16 + c];
            yr += cw * T[c].x;
            yi += cw * T[c].y;
        }
        Xn[o] = make_float2(yr, yi);   // reuse as Ycomb
    }
    __syncthreads();

    // fold fc1: Z[j] = sum_o fc1_w[o][j] * Ycomb[o]   (64 threads, j = t)
    {
        float zr = 0.f, zi = 0.f;
        for (int o = 0; o < 16; o++) {
            float f = fc1_w[o * 64 + t];
            zr += f * Xn[o].x;
            zi += f * Xn[o].y;
        }
        g_Z[(((size_t)b * HID + t) * 8 + kx) * 8 + ky] = make_float2(zr, zi);
    }
}

// ---------------- stage 4: fused per-pixel evaluation ------------------------
// u_j(p) = alpha_j*x + beta_j + sum_ky c_ky*Re( A[b,j,ky,h] * e^{+i ky th_w} )
// out(p) = fc2_b + sum_j fc2_w[j] * relu(u_j)
__global__ void __launch_bounds__(256) k_main(const float* __restrict__ x,
                                              const float* __restrict__ fc2_w,
                                              const float* __restrict__ fc2_b,
                                              float* __restrict__ out) {
    const int b = blockIdx.y, h = blockIdx.x;
    const int tid = threadIdx.x;
    __shared__ __align__(16) float coeff[64][20];

    // row phases e^{+i kx th_h}
    float pc[8], ps[8];
    {
        float s1, c1;
        __sincosf((float)h * TWO_PI_OVER_N, &s1, &c1);
        float ck = 1.f, sk = 0.f;
#pragma unroll
        for (int k = 0; k < 8; k++) {
            pc[k] = ck; ps[k] = sk;
            float cn = ck * c1 - sk * s1;
            float sn = sk * c1 + ck * s1;
            ck = cn; sk = sn;
        }
    }

    // fold row phase into per-row coefficients: A[j][ky] = sum_kx Z[j][kx][ky]*e^{+i kx th_h}
    for (int idx = tid; idx < 512; idx += 256) {
        int j = idx >> 3, ky = idx & 7;
        const float2* zp = g_Z + ((size_t)b * HID + j) * 64 + ky;
        float ar = 0.f, ai = 0.f;
#pragma unroll
        for (int kx = 0; kx < 8; kx++) {
            float2 z = zp[kx * 8];
            ar += z.x * pc[kx] - z.y * ps[kx];
            ai += z.x * ps[kx] + z.y * pc[kx];
        }
        float c = (ky == 0) ? 1.f : 2.f;
        coeff[j][2 * ky]     =  c * ar;
        coeff[j][2 * ky + 1] = -c * ai;
    }
    if (tid < 64) {
        coeff[tid][16] = g_alpha[tid];
        coeff[tid][17] = g_beta[tid];
        coeff[tid][18] = fc2_w[tid];
        coeff[tid][19] = 0.f;
    }
    __syncthreads();

    // two pixels per thread: w = tid, tid+256
    const float* xrow = x + ((size_t)b * HH + h) * WW;
    float xv0 = xrow[tid];
    float xv1 = xrow[tid + 256];

    float b0[16], b1[16];
    {
        float s1, c1;
        __sincosf((float)tid * TWO_PI_OVER_N, &s1, &c1);
        float ck = 1.f, sk = 0.f;
#pragma unroll
        for (int k = 0; k < 8; k++) {
            b0[2 * k] = ck; b0[2 * k + 1] = sk;
            float cn = ck * c1 - sk * s1;
            float sn = sk * c1 + ck * s1;
            ck = cn; sk = sn;
        }
    }
    {
        float s1, c1;
        __sincosf((float)(tid + 256) * TWO_PI_OVER_N, &s1, &c1);
        float ck = 1.f, sk = 0.f;
#pragma unroll
        for (int k = 0; k < 8; k++) {
            b1[2 * k] = ck; b1[2 * k + 1] = sk;
            float cn = ck * c1 - sk * s1;
            float sn = sk * c1 + ck * s1;
            ck = cn; sk = sn;
        }
    }

    float acc0 = 0.f, acc1 = 0.f;
#pragma unroll 4
    for (int j = 0; j < 64; j++) {
        const float4* cj = (const float4*)&coeff[j][0];
        float4 qa = cj[0], qb = cj[1], qc = cj[2], qd = cj[3], qe = cj[4];
        // t=0 basis is 1, t=1 basis is 0 (skipped)
        float u0 = fmaf(qe.x, xv0, qe.y) + qa.x;
        float u1 = fmaf(qe.x, xv1, qe.y) + qa.x;
        u0 = fmaf(qa.z, b0[2],  u0);  u1 = fmaf(qa.z, b1[2],  u1);
        u0 = fmaf(qa.w, b0[3],  u0);  u1 = fmaf(qa.w, b1[3],  u1);
        u0 = fmaf(qb.x, b0[4],  u0);  u1 = fmaf(qb.x, b1[4],  u1);
        u0 = fmaf(qb.y, b0[5],  u0);  u1 = fmaf(qb.y, b1[5],  u1);
        u0 = fmaf(qb.z, b0[6],  u0);  u1 = fmaf(qb.z, b1[6],  u1);
        u0 = fmaf(qb.w, b0[7],  u0);  u1 = fmaf(qb.w, b1[7],  u1);
        u0 = fmaf(qc.x, b0[8],  u0);  u1 = fmaf(qc.x, b1[8],  u1);
        u0 = fmaf(qc.y, b0[9],  u0);  u1 = fmaf(qc.y, b1[9],  u1);
        u0 = fmaf(qc.z, b0[10], u0);  u1 = fmaf(qc.z, b1[10], u1);
        u0 = fmaf(qc.w, b0[11], u0);  u1 = fmaf(qc.w, b1[11], u1);
        u0 = fmaf(qd.x, b0[12], u0);  u1 = fmaf(qd.x, b1[12], u1);
        u0 = fmaf(qd.y, b0[13], u0);  u1 = fmaf(qd.y, b1[13], u1);
        u0 = fmaf(qd.z, b0[14], u0);  u1 = fmaf(qd.z, b1[14], u1);
        u0 = fmaf(qd.w, b0[15], u0);  u1 = fmaf(qd.w, b1[15], u1);
        acc0 = fmaf(qe.z, fmaxf(u0, 0.f), acc0);
        acc1 = fmaf(qe.z, fmaxf(u1, 0.f), acc1);
    }

    float ob = fc2_b[0];
    float* orow = out + ((size_t)b * HH + h) * WW;
    orow[tid]       = acc0 + ob;
    orow[tid + 256] = acc1 + ob;
}

// ---------------- launch -----------------------------------------------------
extern "C" void kernel_launch(void* const* d_in, const int* in_sizes, int n_in,
                              void* d_out, int out_size) {
    const float* x       = (const float*)d_in[0];
    const float* fc0_w   = (const float*)d_in[1];
    const float* fc0_b   = (const float*)d_in[2];
    const float* spec_wr = (const float*)d_in[3];
    const float* spec_wi = (const float*)d_in[4];
    const float* conv_w  = (const float*)d_in[5];
    const float* conv_b  = (const float*)d_in[6];
    const float* fc1_w   = (const float*)d_in[7];
    const float* fc1_b   = (const float*)d_in[8];
    const float* fc2_w   = (const float*)d_in[9];
    const float* fc2_b   = (const float*)d_in[10];
    float* out = (float*)d_out;

    dim3 grid(HH, NB);
    k_rowdft<<<grid, 256>>>(x);
    k_coldft<<<64, 256>>>();
    k_affine<<<1, 64>>>(fc0_w, fc0_b, conv_w, conv_b, fc1_w, fc1_b);
    k_modes<<<512, 64>>>(spec_wr, spec_wi, conv_w, conv_b, fc0_w, fc0_b, fc1_w);
    k_main<<<grid, 256>>>(x, fc2_w, fc2_b, out);
}

// round 4
// speedup vs baseline: 1.2457x; 1.2457x over previous
#include <cuda_runtime.h>

#define HH 512
#define WW 512
#define NB 8
#define CW 16
#define HID 64
#define TWO_PI_OVER_N 0.012271846303085129f  // 2*pi/512

typedef unsigned long long u64;

// ---------------- scratch (static device globals; no allocation) -------------
__device__ float  g_R[NB * HH * 16];               // row DFT of x: [b][h][2*ky{re,im}]
__device__ float  g_Xx[NB * 8 * 8 * 2];            // DFT(x): [b][kx][ky]{re,im} (1/N^2 folded)
__device__ float2 g_Z[NB * HID * 8 * 8];           // folded modes: [b][j][ky][kx]
__device__ float  g_alpha[HID];
__device__ float  g_beta[HID];

// ---------------- f32x2 packed helpers ---------------------------------------
__device__ __forceinline__ u64 pk2(float lo, float hi) {
    u64 r; asm("mov.b64 %0, {%1,%2};" : "=l"(r) : "f"(lo), "f"(hi)); return r;
}
__device__ __forceinline__ void upk2(u64 v, float& lo, float& hi) {
    asm("mov.b64 {%0,%1}, %2;" : "=f"(lo), "=f"(hi) : "l"(v));
}
__device__ __forceinline__ u64 fma2(u64 a, u64 b, u64 c) {
    u64 d; asm("fma.rn.f32x2 %0, %1, %2, %3;" : "=l"(d) : "l"(a), "l"(b), "l"(c)); return d;
}
__device__ __forceinline__ u64 mul2(u64 a, u64 b) {
    u64 d; asm("mul.rn.f32x2 %0, %1, %2;" : "=l"(d) : "l"(a), "l"(b)); return d;
}
__device__ __forceinline__ u64 add2(u64 a, u64 b) {
    u64 d; asm("add.rn.f32x2 %0, %1, %2;" : "=l"(d) : "l"(a), "l"(b)); return d;
}

__device__ __forceinline__ float warp_sum(float v) {
#pragma unroll
    for (int o = 16; o > 0; o >>= 1) v += __shfl_xor_sync(0xffffffffu, v, o);
    return v;
}

// ---------------- stage 1a: per-row partial DFT of x (8 modes, +-256 folded) --
__global__ void __launch_bounds__(256) k_rowdft(const float* __restrict__ x) {
    const int b = blockIdx.y, h = blockIdx.x;
    const int tid = threadIdx.x;
    const float* row = x + ((size_t)b * HH + h) * WW;

    // w = tid in [0,256): fold with w+256 (phase factor (-1)^k)
    float xs = row[tid] + row[tid + 256];
    float xd = row[tid] - row[tid + 256];

    float vr[8], vi[8];
    {
        float s1, c1;
        __sincosf((float)tid * TWO_PI_OVER_N, &s1, &c1);
        float ck = 1.f, sk = 0.f;
#pragma unroll
        for (int k = 0; k < 8; k++) {
            float src = (k & 1) ? xd : xs;
            vr[k] = src * ck;
            vi[k] = -src * sk;
            float cn = ck * c1 - sk * s1;
            float sn = sk * c1 + ck * s1;
            ck = cn; sk = sn;
        }
    }

    float vals[16];
#pragma unroll
    for (int k = 0; k < 8; k++) { vals[2 * k] = vr[k]; vals[2 * k + 1] = vi[k]; }
#pragma unroll
    for (int i = 0; i < 16; i++) vals[i] = warp_sum(vals[i]);

    __shared__ float red[8][16];
    int lane = tid & 31, warp = tid >> 5;
    if (lane == 0) {
#pragma unroll
        for (int i = 0; i < 16; i++) red[warp][i] = vals[i];
    }
    __syncthreads();
    if (tid < 16) {
        float s = 0.f;
#pragma unroll
        for (int w = 0; w < 8; w++) s += red[w][tid];
        g_R[((size_t)b * HH + h) * 16 + tid] = s;
    }
}

// ---------------- stage 1b: column DFT (over h) -> g_Xx[b][kx][ky] ------------
__global__ void __launch_bounds__(256) k_coldft() {
    const int b = blockIdx.x >> 3, ky = blockIdx.x & 7;
    const int tid = threadIdx.x;

    float vr[8], vi[8];
#pragma unroll
    for (int k = 0; k < 8; k++) { vr[k] = 0.f; vi[k] = 0.f; }

    for (int h = tid; h < HH; h += 256) {
        float rr = g_R[((size_t)b * HH + h) * 16 + 2 * ky];
        float ri = g_R[((size_t)b * HH + h) * 16 + 2 * ky + 1];
        float s1, c1;
        __sincosf((float)h * TWO_PI_OVER_N, &s1, &c1);
        float ck = 1.f, sk = 0.f;
#pragma unroll
        for (int k = 0; k < 8; k++) {
            vr[k] += rr * ck + ri * sk;
            vi[k] += ri * ck - rr * sk;
            float cn = ck * c1 - sk * s1;
            float sn = sk * c1 + ck * s1;
            ck = cn; sk = sn;
        }
    }

    float vals[16];
#pragma unroll
    for (int k = 0; k < 8; k++) { vals[2 * k] = vr[k]; vals[2 * k + 1] = vi[k]; }
#pragma unroll
    for (int i = 0; i < 16; i++) vals[i] = warp_sum(vals[i]);

    __shared__ float red[8][16];
    int lane = tid & 31, warp = tid >> 5;
    if (lane == 0) {
#pragma unroll
        for (int i = 0; i < 16; i++) red[warp][i] = vals[i];
    }
    __syncthreads();
    if (tid < 16) {
        float s = 0.f;
#pragma unroll
        for (int w = 0; w < 8; w++) s += red[w][tid];
        int kx = tid >> 1;
        g_Xx[(((size_t)b * 8 + kx) * 8 + ky) * 2 + (tid & 1)] = s * (1.f / (512.f * 512.f));
    }
}

// ---------------- stage 2a: affine chain (alpha/beta, batch independent) ------
__global__ void k_affine(const float* __restrict__ fc0_w, const float* __restrict__ fc0_b,
                         const float* __restrict__ conv_w, const float* __restrict__ conv_b,
                         const float* __restrict__ fc1_w, const float* __restrict__ fc1_b) {
    __shared__ float v[16], bb[16], nv[16], nb[16];
    int t = threadIdx.x;
    if (t < 16) { v[t] = fc0_w[t]; bb[t] = fc0_b[t]; }
    __syncthreads();
    for (int d = 0; d < 3; d++) {
        if (t < 16) {
            float sv = 0.f, sb = 0.f;
            for (int c = 0; c < 16; c++) {
                float cw = conv_w[d * 256 + t * 16 + c];
                sv += cw * v[c];
                sb += cw * bb[c];
            }
            nv[t] = sv;
            nb[t] = sb + conv_b[d * 16 + t];
        }
        __syncthreads();
        if (t < 16) { v[t] = nv[t]; bb[t] = nb[t]; }
        __syncthreads();
    }
    if (t < 64) {
        float a = 0.f, be = 0.f;
        for (int o = 0; o < 16; o++) {
            float f = fc1_w[o * 64 + t];
            a  += f * v[o];
            be += f * bb[o];
        }
        g_alpha[t] = a;
        g_beta[t]  = be + fc1_b[t];
    }
}

// ---------------- stage 2b: mode propagation. 64 blocks (site), 128 thr (b,o) -
__global__ void __launch_bounds__(128) k_modes(const float* __restrict__ spec_wr,
                                               const float* __restrict__ spec_wi,
                                               const float* __restrict__ conv_w,
                                               const float* __restrict__ conv_b,
                                               const float* __restrict__ fc0_w,
                                               const float* __restrict__ fc0_b,
                                               const float* __restrict__ fc1_w) {
    const int site = blockIdx.x;          // kx*8 + ky
    const int kx = site >> 3, ky = site & 7;
    const bool dc = (site == 0);
    const int t = threadIdx.x;            // b = t>>4, o = t&15
    const int b = t >> 4, o = t & 15;

    __shared__ float swr[3][16][16];      // [d][c][o]
    __shared__ float swi[3][16][16];
    __shared__ float scw[768];            // conv_w linear: [d][o][c]
    __shared__ float sfc1[1024];          // fc1_w linear: [o][j]
    __shared__ float2 X[8][16], Y0[8][16], Y1[8][16], Y2[8][16];

    // stage weights (spec weights are stride-64 gathers; done once per block)
    for (int i = t; i < 768; i += 128) {
        swr[0][0][i] = spec_wr[(size_t)i * 64 + site];
        swi[0][0][i] = spec_wi[(size_t)i * 64 + site];
        scw[i] = conv_w[i];
    }
    for (int i = t; i < 1024; i += 128) sfc1[i] = fc1_w[i];

    {
        float xr = g_Xx[((size_t)(b * 8 + kx) * 8 + ky) * 2 + 0];
        float xi = g_Xx[((size_t)(b * 8 + kx) * 8 + ky) * 2 + 1];
        float w0 = fc0_w[o];
        X[b][o] = make_float2(w0 * xr + (dc ? fc0_b[o] : 0.f), w0 * xi);
    }
    __syncthreads();

    for (int d = 0; d < 3; d++) {
        float yr = 0.f, yi = 0.f;
#pragma unroll
        for (int c = 0; c < 16; c++) {
            float wr = swr[d][c][o], wim = swi[d][c][o];
            float xr = X[b][c].x, xi = X[b][c].y;
            yr += xr * wr - xi * wim;
            yi += xr * wim + xi * wr;
        }
        if (d == 0) Y0[b][o] = make_float2(yr, yi);
        else if (d == 1) Y1[b][o] = make_float2(yr, yi);
        else Y2[b][o] = make_float2(yr, yi);

        // band-fold: DFT of the inverse transform of the kept band
        float gyr = yr, gyi = yi;
        if (ky == 0) {
            if (kx == 0) gyi = 0.f;
            else { gyr *= 0.5f; gyi *= 0.5f; }
        }
        float nr = gyr, ni = gyi;
#pragma unroll
        for (int c = 0; c < 16; c++) {
            float cw = scw[d * 256 + o * 16 + c];
            nr += cw * X[b][c].x;
            ni += cw * X[b][c].y;
        }
        if (dc) nr += conv_b[d * 16 + o];
        __syncthreads();
        X[b][o] = make_float2(nr, ni);
        __syncthreads();
    }

    // Ycomb = Y2 + C2*(Y1 + C1*Y0)   (conv matrices of layers 1 and 2)
    {
        float tr = Y1[b][o].x, ti = Y1[b][o].y;
#pragma unroll
        for (int c = 0; c < 16; c++) {
            float cw = scw[1 * 256 + o * 16 + c];
            tr += cw * Y0[b][c].x;
            ti += cw * Y0[b][c].y;
        }
        __syncthreads();
        X[b][o] = make_float2(tr, ti);   // X := T
        __syncthreads();
        float yr = Y2[b][o].x, yi = Y2[b][o].y;
#pragma unroll
        for (int c = 0; c < 16; c++) {
            float cw = scw[2 * 256 + o * 16 + c];
            yr += cw * X[b][c].x;
            yi += cw * X[b][c].y;
        }
        __syncthreads();
        Y0[b][o] = make_float2(yr, yi);  // Y0 := Ycomb
        __syncthreads();
    }

    // fold fc1: Z[b][j] = sum_o fc1_w[o][j] * Ycomb[b][o]; layout [b][j][ky][kx]
#pragma unroll
    for (int r = 0; r < 4; r++) {
        int j = (t & 15) + 16 * r;
        float zr = 0.f, zi = 0.f;
#pragma unroll
        for (int o2 = 0; o2 < 16; o2++) {
            float f = sfc1[o2 * 64 + j];
            zr += f * Y0[b][o2].x;
            zi += f * Y0[b][o2].y;
        }
        g_Z[(((size_t)b * HID + j) * 8 + ky) * 8 + kx] = make_float2(zr, zi);
    }
}

// ---------------- stage 4: fused per-pixel evaluation (E/O split + f32x2) -----
// 128 threads per (b,h); thread covers pixels {tid, tid+128, tid+256, tid+384}.
// lanes of f32x2 = base pixels (tid, tid+128); E/O split gives +256 partners.
__global__ void __launch_bounds__(128) k_main(const float* __restrict__ x,
                                              const float* __restrict__ fc2_w,
                                              const float* __restrict__ fc2_b,
                                              float* __restrict__ out) {
    const int b = blockIdx.y, h = blockIdx.x;
    const int tid = threadIdx.x;

    // packed coeff table: slots 0-5 E(ky=2,4,6 cos/sin), 6-13 O(ky=1,3,5,7),
    // 14 alpha, 15 beta+c0  (each u64 = value broadcast to both f32 lanes)
    __shared__ __align__(16) u64 tab[64][16];
    __shared__ float s_fc2[64];

    // row phases e^{+i kx th_h}
    float pc[8], ps[8];
    {
        float s1, c1;
        __sincosf((float)h * TWO_PI_OVER_N, &s1, &c1);
        float ck = 1.f, sk = 0.f;
#pragma unroll
        for (int k = 0; k < 8; k++) {
            pc[k] = ck; ps[k] = sk;
            float cn = ck * c1 - sk * s1;
            float sn = sk * c1 + ck * s1;
            ck = cn; sk = sn;
        }
    }

    // fold row phase into per-row packed coefficients
    for (int r = 0; r < 4; r++) {
        int idx = tid + 128 * r;          // j*8 + ky
        int j = idx >> 3, ky = idx & 7;
        const float4* zp = (const float4*)(g_Z + (((size_t)b * HID + j) * 8 + ky) * 8);
        float4 z01 = zp[0], z23 = zp[1], z45 = zp[2], z67 = zp[3];
        float ar, ai;
        ar  = z01.x * pc[0] - z01.y * ps[0];  ai  = z01.x * ps[0] + z01.y * pc[0];
        ar += z01.z * pc[1] - z01.w * ps[1];  ai += z01.z * ps[1] + z01.w * pc[1];
        ar += z23.x * pc[2] - z23.y * ps[2];  ai += z23.x * ps[2] + z23.y * pc[2];
        ar += z23.z * pc[3] - z23.w * ps[3];  ai += z23.z * ps[3] + z23.w * pc[3];
        ar += z45.x * pc[4] - z45.y * ps[4];  ai += z45.x * ps[4] + z45.y * pc[4];
        ar += z45.z * pc[5] - z45.w * ps[5];  ai += z45.z * ps[5] + z45.w * pc[5];
        ar += z67.x * pc[6] - z67.y * ps[6];  ai += z67.x * ps[6] + z67.y * pc[6];
        ar += z67.z * pc[7] - z67.w * ps[7];  ai += z67.z * ps[7] + z67.w * pc[7];

        if (ky == 0) {
            // c0 = Re(A); fold into beta; also stash alpha/fc2
            float bc0 = g_beta[j] + ar;
            float al = g_alpha[j];
            tab[j][14] = pk2(al, al);
            tab[j][15] = pk2(bc0, bc0);
            s_fc2[j] = fc2_w[j];
        } else {
            float ccos = 2.f * ar, csin = -2.f * ai;
            int slot = (ky & 1) ? (5 + ky) : (ky - 2);
            tab[j][slot]     = pk2(ccos, ccos);
            tab[j][slot + 1] = pk2(csin, csin);
        }
    }

    // per-thread basis for base pixels w0=tid, w1=tid+128 (packed into lanes)
    float b0[16], b1[16];
    {
        float s1, c1;
        __sincosf((float)tid * TWO_PI_OVER_N, &s1, &c1);
        float ck = 1.f, sk = 0.f;
#pragma unroll
        for (int k = 0; k < 8; k++) {
            b0[2 * k] = ck; b0[2 * k + 1] = sk;
            float cn = ck * c1 - sk * s1;
            float sn = sk * c1 + ck * s1;
            ck = cn; sk = sn;
        }
    }
    {
        float s1, c1;
        __sincosf((float)(tid + 128) * TWO_PI_OVER_N, &s1, &c1);
        float ck = 1.f, sk = 0.f;
#pragma unroll
        for (int k = 0; k < 8; k++) {
            b1[2 * k] = ck; b1[2 * k + 1] = sk;
            float cn = ck * c1 - sk * s1;
            float sn = sk * c1 + ck * s1;
            ck = cn; sk = sn;
        }
    }
    // E basis: ky=2,4,6 (cos,sin); O basis: ky=1,3,5,7
    u64 bE0 = pk2(b0[4],  b1[4]),  bE1 = pk2(b0[5],  b1[5]);
    u64 bE2 = pk2(b0[8],  b1[8]),  bE3 = pk2(b0[9],  b1[9]);
    u64 bE4 = pk2(b0[12], b1[12]), bE5 = pk2(b0[13], b1[13]);
    u64 bO0 = pk2(b0[2],  b1[2]),  bO1 = pk2(b0[3],  b1[3]);
    u64 bO2 = pk2(b0[6],  b1[6]),  bO3 = pk2(b0[7],  b1[7]);
    u64 bO4 = pk2(b0[10], b1[10]), bO5 = pk2(b0[11], b1[11]);
    u64 bO6 = pk2(b0[14], b1[14]), bO7 = pk2(b0[15], b1[15]);

    const float* xrow = x + ((size_t)b * HH + h) * WW;
    u64 xpa = pk2(xrow[tid],       xrow[tid + 128]);
    u64 xpb = pk2(xrow[tid + 256], xrow[tid + 384]);
    const u64 NEG1 = pk2(-1.f, -1.f);

    __syncthreads();

    float acc0 = 0.f, acc1 = 0.f, acc2 = 0.f, acc3 = 0.f;
#pragma unroll 2
    for (int j = 0; j < 64; j++) {
        const ulonglong2* tj = (const ulonglong2*)(&tab[j][0]);
        ulonglong2 q0 = tj[0], q1 = tj[1], q2 = tj[2], q3 = tj[3];
        ulonglong2 q4 = tj[4], q5 = tj[5], q6 = tj[6], q7 = tj[7];

        u64 e = mul2(q0.x, bE0);
        e = fma2(q0.y, bE1, e);
        e = fma2(q1.x, bE2, e);
        e = fma2(q1.y, bE3, e);
        e = fma2(q2.x, bE4, e);
        e = fma2(q2.y, bE5, e);

        u64 o = mul2(q3.x, bO0);
        o = fma2(q3.y, bO1, o);
        o = fma2(q4.x, bO2, o);
        o = fma2(q4.y, bO3, o);
        o = fma2(q5.x, bO4, o);
        o = fma2(q5.y, bO5, o);
        o = fma2(q6.x, bO6, o);
        o = fma2(q6.y, bO7, o);

        u64 ba = fma2(q7.x, xpa, q7.y);   // alpha*x + (beta+c0), pixels (w0,w1)
        u64 bb_ = fma2(q7.x, xpb, q7.y);  // pixels (w0+256, w1+256)
        u64 ua = add2(ba, add2(e, o));
        u64 ub = add2(bb_, fma2(o, NEG1, e));

        float ua0, ua1, ub0, ub1;
        upk2(ua, ua0, ua1);
        upk2(ub, ub0, ub1);
        float w2 = s_fc2[j];
        acc0 = fmaf(w2, fmaxf(ua0, 0.f), acc0);
        acc1 = fmaf(w2, fmaxf(ua1, 0.f), acc1);
        acc2 = fmaf(w2, fmaxf(ub0, 0.f), acc2);
        acc3 = fmaf(w2, fmaxf(ub1, 0.f), acc3);
    }

    float ob = fc2_b[0];
    float* orow = out + ((size_t)b * HH + h) * WW;
    orow[tid]       = acc0 + ob;
    orow[tid + 128] = acc1 + ob;
    orow[tid + 256] = acc2 + ob;
    orow[tid + 384] = acc3 + ob;
}

// ---------------- launch -----------------------------------------------------
extern "C" void kernel_launch(void* const* d_in, const int* in_sizes, int n_in,
                              void* d_out, int out_size) {
    const float* x       = (const float*)d_in[0];
    const float* fc0_w   = (const float*)d_in[1];
    const float* fc0_b   = (const float*)d_in[2];
    const float* spec_wr = (const float*)d_in[3];
    const float* spec_wi = (const float*)d_in[4];
    const float* conv_w  = (const float*)d_in[5];
    const float* conv_b  = (const float*)d_in[6];
    const float* fc1_w   = (const float*)d_in[7];
    const float* fc1_b   = (const float*)d_in[8];
    const float* fc2_w   = (const float*)d_in[9];
    const float* fc2_b   = (const float*)d_in[10];
    float* out = (float*)d_out;

    dim3 grid(HH, NB);
    k_rowdft<<<grid, 256>>>(x);
    k_coldft<<<64, 256>>>();
    k_affine<<<1, 64>>>(fc0_w, fc0_b, conv_w, conv_b, fc1_w, fc1_b);
    k_modes<<<64, 128>>>(spec_wr, spec_wi, conv_w, conv_b, fc0_w, fc0_b, fc1_w);
    k_main<<<grid, 128>>>(x, fc2_w, fc2_b, out);
}